// round 11
// baseline (speedup 1.0000x reference)
#include <cuda_runtime.h>
#include <cuda_fp16.h>
#include <float.h>
#include <stdint.h>

// Problem constants
#define B_   4
#define T_   4096
#define DIN  1024
#define H_   16
#define D_   64
#define M_   (B_*T_)        // 16384
#define N_   (H_*D_*2)      // 2048
#define CH   64
#define NC   (T_/CH)

// Scratch
__device__ float g_v[(size_t)B_*H_*T_*D_];    // relu(v) fp32 [b][h][t][d] 64 MB
__device__ float g_st[(size_t)B_*H_*T_];      // scores   [b][h][t]
__device__ float g_cm[B_*H_*NC];
__device__ float g_cu[B_*H_*NC];
__device__ float g_cw[B_*H_*NC*D_];
__device__ __half g_A16[(size_t)M_*DIN];      // fp16(A)           32 MB
__device__ __half g_B16[(size_t)N_*DIN];      // transposed [n][k]  4 MB

// ---------------------------------------------------------------------------
// PTX helpers (sm_80-compatible only: cp.async, ldmatrix, mma.sync)
// ---------------------------------------------------------------------------
__device__ __forceinline__ uint32_t smem_u32(const void* p) {
    return (uint32_t)__cvta_generic_to_shared(p);
}
#define CP_ASYNC16(dst, src) \
    asm volatile("cp.async.cg.shared.global [%0], [%1], 16;" :: "r"(dst), "l"(src) : "memory")
#define CP_COMMIT() asm volatile("cp.async.commit_group;" ::: "memory")
#define CP_WAIT(n)  asm volatile("cp.async.wait_group %0;" :: "n"(n) : "memory")

#define LDSM_X4(r0, r1, r2, r3, addr) \
    asm volatile("ldmatrix.sync.aligned.m8n8.x4.shared.b16 {%0,%1,%2,%3}, [%4];" \
                 : "=r"(r0), "=r"(r1), "=r"(r2), "=r"(r3) : "r"(addr))

#define MMA_16816(d, a, b) \
    asm volatile("mma.sync.aligned.m16n8k16.row.col.f32.f16.f16.f32 " \
                 "{%0,%1,%2,%3},{%4,%5,%6,%7},{%8,%9},{%0,%1,%2,%3};" \
                 : "+f"((d)[0]), "+f"((d)[1]), "+f"((d)[2]), "+f"((d)[3]) \
                 : "r"((a)[0]), "r"((a)[1]), "r"((a)[2]), "r"((a)[3]), \
                   "r"((b)[0]), "r"((b)[1]))

#define SW128(o) ((o) ^ (((o) >> 3) & 0x70))

// ---------------------------------------------------------------------------
// Conversion kernels
// ---------------------------------------------------------------------------
__global__ __launch_bounds__(256) void convA_kernel(const float* __restrict__ A)
{
    const size_t idx = (size_t)blockIdx.x * 256 + threadIdx.x;   // float4 index
    float4 a = ((const float4*)A)[idx];
    __half2* hp = (__half2*)&g_A16[idx * 4];
    hp[0] = __floats2half2_rn(a.x, a.y);
    hp[1] = __floats2half2_rn(a.z, a.w);
}

__global__ __launch_bounds__(256) void convB_kernel(const float* __restrict__ Bsrc)
{
    __shared__ float tile[32][33];
    const int tx = threadIdx.x;      // 0..31
    const int ty = threadIdx.y;      // 0..7
    const int n0 = blockIdx.x * 32;
    const int k0 = blockIdx.y * 32;
#pragma unroll
    for (int r = 0; r < 4; r++)
        tile[ty + r * 8][tx] = Bsrc[(size_t)(k0 + ty + r * 8) * N_ + n0 + tx];
    __syncthreads();
#pragma unroll
    for (int r = 0; r < 4; r++) {
        const float v = tile[tx][ty + r * 8];
        const size_t o = (size_t)(n0 + ty + r * 8) * DIN + k0 + tx;
        g_B16[o] = __float2half_rn(v);
    }
}

// ---------------------------------------------------------------------------
// HMMA GEMM: CTA 128(M) x 256(N = 2 heads), 512 threads / 16 warps,
// warp tile 32x64 (4 warps/SMSP for latency hiding), K-step 64, 16 K-tiles,
// 3-stage cp.async pipeline (R5 ordering). fp32 accumulation.
// Fused epilogue: relu, st = q.k, v store, per-chunk scan carries
// (two-level: per-warp 32-row partials -> pairwise combine via smem).
// ---------------------------------------------------------------------------
#define NT   16
#define NTHR 512
#define STAGE_A   16384          // 128 rows * 128B
#define STAGE_B   32768          // 256 rows * 128B
#define STAGE_BYTES (STAGE_A + STAGE_B)         // 49152
#define SMEM_TOTAL (3 * STAGE_BYTES)            // 147456

__device__ __forceinline__ void load_tile(uint32_t sbase, int i, int s,
                                          int m0, int n0, int tid)
{
    const int kt = i * 64;
    const uint32_t aoff = s * STAGE_BYTES;
    const uint32_t boff = aoff + STAGE_A;
#pragma unroll
    for (int r = 0; r < 2; r++) {
        const int idx = tid + r * NTHR;            // 0..1023
        const int row = idx >> 3, cc = idx & 7;
        const uint64_t src = __cvta_generic_to_global(g_A16 + (size_t)(m0 + row) * DIN + kt + cc * 8);
        CP_ASYNC16(sbase + aoff + SW128(row * 128 + cc * 16), src);
    }
#pragma unroll
    for (int r = 0; r < 4; r++) {
        const int idx = tid + r * NTHR;            // 0..2047
        const int row = idx >> 3, cc = idx & 7;
        const uint64_t src = __cvta_generic_to_global(g_B16 + (size_t)(n0 + row) * DIN + kt + cc * 8);
        CP_ASYNC16(sbase + boff + SW128(row * 128 + cc * 16), src);
    }
    CP_COMMIT();
}

__global__ __launch_bounds__(NTHR, 1) void gemm_mma_kernel(const float* __restrict__ q)
{
    extern __shared__ char smem[];
    const uint32_t sbase = smem_u32(smem);
    const int tid  = threadIdx.x;
    const int w    = tid >> 5;              // 0..15
    const int lane = tid & 31;
    const int ny = blockIdx.x;              // 0..7 (fast: A-tile reuse in L2)
    const int m0 = blockIdx.y * 128;
    const int n0 = ny * 256;
    const int wm = w >> 2;                  // 0..3 (32 M-rows each)
    const int wn = w & 3;                   // 0..3 (64 N-cols each)

    float acc[2][8][4];
#pragma unroll
    for (int mi = 0; mi < 2; mi++)
#pragma unroll
        for (int n8 = 0; n8 < 8; n8++)
#pragma unroll
            for (int c = 0; c < 4; c++) acc[mi][n8][c] = 0.f;

    // prologue: stages 0,1 in flight
    load_tile(sbase, 0, 0, m0, n0, tid);
    load_tile(sbase, 1, 1, m0, n0, tid);

    // precomputed ldmatrix lane-address components
    const int aT  = lane >> 3;                       // 0..3
    const int arow_l = ((aT & 1) << 3) + (lane & 7); // +8 rows for odd T
    const int akb_l  = (aT >> 1) << 4;               // +16B for T>=2
    const int brow_l = (((lane >> 4) & 1) << 3) + (lane & 7);
    const int bkb_l  = ((lane >> 3) & 1) << 4;

    for (int i = 0; i < NT; i++) {
        if (i + 2 < NT) load_tile(sbase, i + 2, (i + 2) % 3, m0, n0, tid);
        const int rem = NT - 1 - i;
        if (rem >= 2)      CP_WAIT(2);
        else if (rem == 1) CP_WAIT(1);
        else               CP_WAIT(0);
        __syncthreads();

        const uint32_t sA = sbase + (i % 3) * STAGE_BYTES;
        const uint32_t sB = sA + STAGE_A;

#pragma unroll
        for (int kk = 0; kk < 4; kk++) {
            uint32_t a[2][4];
#pragma unroll
            for (int mi = 0; mi < 2; mi++) {
                const int row = wm * 32 + mi * 16 + arow_l;
                const int kb  = kk * 32 + akb_l;
                LDSM_X4(a[mi][0], a[mi][1], a[mi][2], a[mi][3],
                        sA + SW128(row * 128 + kb));
            }
            uint32_t bf[8][2];
#pragma unroll
            for (int np = 0; np < 4; np++) {
                const int nrow = wn * 64 + np * 16 + brow_l;
                const int kb   = kk * 32 + bkb_l;
                LDSM_X4(bf[np * 2][0], bf[np * 2][1],
                        bf[np * 2 + 1][0], bf[np * 2 + 1][1],
                        sB + SW128(nrow * 128 + kb));
            }
#pragma unroll
            for (int mi = 0; mi < 2; mi++)
#pragma unroll
                for (int n8 = 0; n8 < 8; n8++)
                    MMA_16816(acc[mi][n8], a[mi], bf[n8]);
        }
        __syncthreads();
    }

    // -----------------------------------------------------------------------
    // Epilogue A: relu, write v, per-row st partials to smem.
    // Column pairing: c0/c2 = k, c1/c3 = v.  d = (wn&1)*32 + n8*4 + (lane&3).
    // Head h = ny*2 + (wn>>1). Warp rows: wm*32 .. wm*32+31.
    // -----------------------------------------------------------------------
    const int h     = ny * 2 + (wn >> 1);
    const int dbase = (wn & 1) * 32 + (lane & 3);
    float qreg[8];
#pragma unroll
    for (int n8 = 0; n8 < 8; n8++) qreg[n8] = q[h * D_ + dbase + n8 * 4];

    float* st_buf  = (float*)smem;                 // [128][4]
    float* st_tot  = (float*)(smem + 2048);        // [2][128]
    float* sm_part = (float*)(smem + 3072);        // [16][34] carry partials

#pragma unroll
    for (int mi = 0; mi < 2; mi++) {
        const int rl0 = wm * 32 + mi * 16 + (lane >> 2);
        float st0 = 0.f, st1 = 0.f;
#pragma unroll
        for (int n8 = 0; n8 < 8; n8++) {
            const int d = dbase + n8 * 4;
            const float k0 = fmaxf(acc[mi][n8][0], 0.f);
            const float v0 = fmaxf(acc[mi][n8][1], 0.f);
            const float k1 = fmaxf(acc[mi][n8][2], 0.f);
            const float v1 = fmaxf(acc[mi][n8][3], 0.f);
            st0 += qreg[n8] * k0;
            st1 += qreg[n8] * k1;
            {
                const int m = m0 + rl0;
                const int b = m >> 12, t = m & 4095;
                g_v[((size_t)(b * H_ + h) * T_ + t) * D_ + d] = v0;
            }
            {
                const int m = m0 + rl0 + 8;
                const int b = m >> 12, t = m & 4095;
                g_v[((size_t)(b * H_ + h) * T_ + t) * D_ + d] = v1;
            }
        }
        st0 += __shfl_xor_sync(0xffffffffu, st0, 1);
        st0 += __shfl_xor_sync(0xffffffffu, st0, 2);
        st1 += __shfl_xor_sync(0xffffffffu, st1, 1);
        st1 += __shfl_xor_sync(0xffffffffu, st1, 2);
        if ((lane & 3) == 0) {
            st_buf[rl0 * 4 + wn]       = st0;
            st_buf[(rl0 + 8) * 4 + wn] = st1;
        }
    }
    __syncthreads();

    if (tid < 128) {
        const int m = m0 + tid;
        const int b = m >> 12, t = m & 4095;
        const float s0 = st_buf[tid * 4 + 0] + st_buf[tid * 4 + 1];
        const float s1 = st_buf[tid * 4 + 2] + st_buf[tid * 4 + 3];
        g_st[(size_t)(b * H_ + ny * 2) * T_ + t]     = s0;
        g_st[(size_t)(b * H_ + ny * 2 + 1) * T_ + t] = s1;
        st_tot[tid]       = s0;
        st_tot[128 + tid] = s1;
    }
    __syncthreads();

    // -----------------------------------------------------------------------
    // Epilogue B (fused scan phase 1, two-level): commutative combine.
    // Level 1: each warp reduces its 32 rows -> partial (m,u,w[32]) in smem.
    // Level 2: warps with even wm combine (wm, wm+1) -> chunk wm>>1 carry.
    // -----------------------------------------------------------------------
    {
        const int hh = wn >> 1;
        const int r  = lane >> 2;
        float mloc = -FLT_MAX;
#pragma unroll
        for (int mi = 0; mi < 2; mi++) {
            mloc = fmaxf(mloc, st_tot[hh * 128 + wm * 32 + mi * 16 + r]);
            mloc = fmaxf(mloc, st_tot[hh * 128 + wm * 32 + mi * 16 + 8 + r]);
        }
        float uloc = 0.f, wloc[8];
#pragma unroll
        for (int n8 = 0; n8 < 8; n8++) wloc[n8] = 0.f;
#pragma unroll
        for (int mi = 0; mi < 2; mi++) {
            const float s0 = st_tot[hh * 128 + wm * 32 + mi * 16 + r];
            const float s1 = st_tot[hh * 128 + wm * 32 + mi * 16 + 8 + r];
            const float e0 = __expf(s0 - mloc);
            const float e1 = __expf(s1 - mloc);
            uloc += e0 + e1;
#pragma unroll
            for (int n8 = 0; n8 < 8; n8++) {
                wloc[n8] += e0 * fmaxf(acc[mi][n8][1], 0.f)
                          + e1 * fmaxf(acc[mi][n8][3], 0.f);
            }
        }
        // butterfly over lane bits 2..4 (r dimension)
#pragma unroll
        for (int off = 4; off <= 16; off <<= 1) {
            const float m2 = __shfl_xor_sync(0xffffffffu, mloc, off);
            const float u2 = __shfl_xor_sync(0xffffffffu, uloc, off);
            const float mn = fmaxf(mloc, m2);
            const float ea = __expf(mloc - mn);
            const float eb = __expf(m2 - mn);
            uloc = uloc * ea + u2 * eb;
#pragma unroll
            for (int n8 = 0; n8 < 8; n8++) {
                const float w2 = __shfl_xor_sync(0xffffffffu, wloc[n8], off);
                wloc[n8] = wloc[n8] * ea + w2 * eb;
            }
            mloc = mn;
        }
        // level-1 partial to smem: d_local = (lane&3) + n8*4 (lanes 0..3)
        if (lane < 4) {
#pragma unroll
            for (int n8 = 0; n8 < 8; n8++)
                sm_part[w * 34 + 2 + lane + n8 * 4] = wloc[n8];
            if (lane == 0) {
                sm_part[w * 34 + 0] = mloc;
                sm_part[w * 34 + 1] = uloc;
            }
        }
    }
    __syncthreads();

    if ((wm & 1) == 0) {
        const int pw = w + 4;                // partner warp (wm+1, same wn)
        const float m1 = sm_part[w * 34 + 0];
        const float u1 = sm_part[w * 34 + 1];
        const float w1v = sm_part[w * 34 + 2 + lane];
        const float m2 = sm_part[pw * 34 + 0];
        const float u2 = sm_part[pw * 34 + 1];
        const float w2v = sm_part[pw * 34 + 2 + lane];
        const float mn = fmaxf(m1, m2);
        const float ea = __expf(m1 - mn);
        const float eb = __expf(m2 - mn);
        const float uu = u1 * ea + u2 * eb;
        const float wv = w1v * ea + w2v * eb;

        const int b   = m0 >> 12;
        const int cch = ((m0 & 4095) >> 6) + (wm >> 1);
        const size_t ci = (size_t)(b * H_ + h) * NC + cch;
        g_cw[ci * D_ + (wn & 1) * 32 + lane] = wv;
        if (lane == 0 && (wn & 1) == 0) { g_cm[ci] = mn; g_cu[ci] = uu; }
    }
}

// ---------------------------------------------------------------------------
// Phase 2: per-(b,h) block, carries staged once through smem (verified win).
// ---------------------------------------------------------------------------
__global__ __launch_bounds__(64) void scan_phase2_kernel()
{
    __shared__ float sm_m[NC], sm_u[NC], sm_w[NC][D_];
    const int bh = blockIdx.x;
    const int d  = threadIdx.x;   // 0..63

    sm_m[d] = g_cm[(size_t)bh * NC + d];
    sm_u[d] = g_cu[(size_t)bh * NC + d];
    for (int c = 0; c < NC; c++)
        sm_w[c][d] = g_cw[((size_t)bh * NC + c) * D_ + d];
    __syncthreads();

    float m = -FLT_MAX, u = 0.f, w = 0.f;
    for (int c = 0; c < NC; c++) {
        const float cm = sm_m[c];
        const float cu = sm_u[c];
        const float cw = sm_w[c][d];
        g_cw[((size_t)bh * NC + c) * D_ + d] = w;
        if (d == 0) { g_cm[(size_t)bh * NC + c] = m; g_cu[(size_t)bh * NC + c] = u; }

        const float mn = fmaxf(m, cm);
        const float ea = __expf(m - mn);
        const float eb = __expf(cm - mn);
        u = u * ea + cu * eb;
        w = w * ea + cw * eb;
        m = mn;
    }
}

// ---------------------------------------------------------------------------
// Phase 3 (independent warps + REDG atomics — verified fastest variant):
// per-(b,h,chunk) warp re-scans its chunk from the chunk prefix,
// out[b,t,d] += w/u via atomicAdd.
// ---------------------------------------------------------------------------
__global__ __launch_bounds__(256) void scan_phase3_kernel(float* __restrict__ out)
{
    const int gw   = (blockIdx.x * blockDim.x + threadIdx.x) >> 5;
    const int lane = threadIdx.x & 31;
    const int c  = gw % NC;
    const int bh = gw / NC;
    const int b  = bh >> 4;

    const size_t ci = (size_t)bh * NC + c;
    float m  = g_cm[ci];
    float u  = g_cu[ci];
    float w0 = g_cw[ci * D_ + lane];
    float w1 = g_cw[ci * D_ + 32 + lane];

    const float* vp  = g_v  + ((size_t)bh * T_ + c * CH) * D_;
    const float* stp = g_st + (size_t)bh * T_ + c * CH;
    float* op = out + ((size_t)b * T_ + c * CH) * D_;

    for (int i = 0; i < CH; i++) {
        const float st = stp[i];
        const float v0 = vp[i * D_ + lane];
        const float v1 = vp[i * D_ + 32 + lane];
        const float mn = fmaxf(m, st);
        const float ea = __expf(m - mn);
        const float eb = __expf(st - mn);
        u  = u  * ea + eb;
        w0 = w0 * ea + v0 * eb;
        w1 = w1 * ea + v1 * eb;
        m = mn;
        const float inv = __fdividef(1.f, u);
        atomicAdd(&op[i * D_ + lane],      w0 * inv);
        atomicAdd(&op[i * D_ + 32 + lane], w1 * inv);
    }
}

// ---------------------------------------------------------------------------
extern "C" void kernel_launch(void* const* d_in, const int* in_sizes, int n_in,
                              void* d_out, int out_size)
{
    const float* inp = nullptr;
    const float* kvk = nullptr;
    const float* qk  = nullptr;
    for (int i = 0; i < n_in; i++) {
        if (in_sizes[i] == B_ * T_ * DIN)          inp = (const float*)d_in[i];
        else if (in_sizes[i] == DIN * H_ * D_ * 2) kvk = (const float*)d_in[i];
        else if (in_sizes[i] == H_ * D_)           qk  = (const float*)d_in[i];
    }
    float* out = (float*)d_out;

    cudaFuncSetAttribute(gemm_mma_kernel,
                         cudaFuncAttributeMaxDynamicSharedMemorySize, SMEM_TOTAL);

    cudaMemsetAsync(out, 0, (size_t)out_size * sizeof(float));

    convA_kernel<<<(M_ * DIN / 4) / 256, 256>>>(inp);
    convB_kernel<<<dim3(N_ / 32, DIN / 32), dim3(32, 8)>>>(kvk);

    dim3 ggrid(8, M_ / 128);
    gemm_mma_kernel<<<ggrid, NTHR, SMEM_TOTAL>>>(qk);

    scan_phase2_kernel<<<B_ * H_, 64>>>();
    scan_phase3_kernel<<<(B_ * H_ * NC) / 8, 256>>>(out);
}

// round 13
// speedup vs baseline: 1.0806x; 1.0806x over previous
#include <cuda_runtime.h>
#include <cuda_fp16.h>
#include <float.h>
#include <stdint.h>

// Problem constants
#define B_   4
#define T_   4096
#define DIN  1024
#define H_   16
#define D_   64
#define M_   (B_*T_)        // 16384
#define N_   (H_*D_*2)      // 2048
#define CH   64
#define NC   (T_/CH)

// Scratch
__device__ float g_v[(size_t)B_*H_*T_*D_];    // relu(v) fp32 [b][h][t][d] 64 MB
__device__ float g_st[(size_t)B_*H_*T_];      // scores   [b][h][t]
__device__ float g_cm[B_*H_*NC];
__device__ float g_cu[B_*H_*NC];
__device__ float g_cw[B_*H_*NC*D_];
__device__ __half g_A16[(size_t)M_*DIN];      // fp16(A)           32 MB
__device__ __half g_B16[(size_t)N_*DIN];      // transposed [n][k]  4 MB

// ---------------------------------------------------------------------------
// PTX helpers (sm_80-compatible only: cp.async, ldmatrix, mma.sync)
// ---------------------------------------------------------------------------
__device__ __forceinline__ uint32_t smem_u32(const void* p) {
    return (uint32_t)__cvta_generic_to_shared(p);
}
#define CP_ASYNC16(dst, src) \
    asm volatile("cp.async.cg.shared.global [%0], [%1], 16;" :: "r"(dst), "l"(src) : "memory")
#define CP_COMMIT() asm volatile("cp.async.commit_group;" ::: "memory")
#define CP_WAIT(n)  asm volatile("cp.async.wait_group %0;" :: "n"(n) : "memory")

#define LDSM_X4(r0, r1, r2, r3, addr) \
    asm volatile("ldmatrix.sync.aligned.m8n8.x4.shared.b16 {%0,%1,%2,%3}, [%4];" \
                 : "=r"(r0), "=r"(r1), "=r"(r2), "=r"(r3) : "r"(addr))

#define MMA_16816(d, a, b) \
    asm volatile("mma.sync.aligned.m16n8k16.row.col.f32.f16.f16.f32 " \
                 "{%0,%1,%2,%3},{%4,%5,%6,%7},{%8,%9},{%0,%1,%2,%3};" \
                 : "+f"((d)[0]), "+f"((d)[1]), "+f"((d)[2]), "+f"((d)[3]) \
                 : "r"((a)[0]), "r"((a)[1]), "r"((a)[2]), "r"((a)[3]), \
                   "r"((b)[0]), "r"((b)[1]))

#define SW128(o) ((o) ^ (((o) >> 3) & 0x70))

// ---------------------------------------------------------------------------
// Conversion kernels
// ---------------------------------------------------------------------------
__global__ __launch_bounds__(256) void convA_kernel(const float* __restrict__ A)
{
    const size_t idx = (size_t)blockIdx.x * 256 + threadIdx.x;   // float4 index
    float4 a = ((const float4*)A)[idx];
    __half2* hp = (__half2*)&g_A16[idx * 4];
    hp[0] = __floats2half2_rn(a.x, a.y);
    hp[1] = __floats2half2_rn(a.z, a.w);
}

__global__ __launch_bounds__(256) void convB_kernel(const float* __restrict__ Bsrc)
{
    __shared__ float tile[32][33];
    const int tx = threadIdx.x;      // 0..31
    const int ty = threadIdx.y;      // 0..7
    const int n0 = blockIdx.x * 32;
    const int k0 = blockIdx.y * 32;
#pragma unroll
    for (int r = 0; r < 4; r++)
        tile[ty + r * 8][tx] = Bsrc[(size_t)(k0 + ty + r * 8) * N_ + n0 + tx];
    __syncthreads();
#pragma unroll
    for (int r = 0; r < 4; r++) {
        const float v = tile[tx][ty + r * 8];
        const size_t o = (size_t)(n0 + ty + r * 8) * DIN + k0 + tx;
        g_B16[o] = __float2half_rn(v);
    }
}

// ---------------------------------------------------------------------------
// HMMA GEMM: CTA 128(M) x 256(N = 2 heads), 8 warps, warp tile 64x64,
// K-step 64, 16 K-tiles. 4-stage cp.async pipeline with ONE barrier per
// tile (wait(2) -> sync -> issue load(i+3) -> compute), and kk-level
// operand double-buffering so LDSM latency is exposed once per tile.
// fp32 accumulation. Fused epilogue: relu, st = q.k, v store, chunk carries.
// ---------------------------------------------------------------------------
#define NT   16
#define STAGE_A   16384          // 128 rows * 128B
#define STAGE_B   32768          // 256 rows * 128B
#define STAGE_BYTES (STAGE_A + STAGE_B)         // 49152
#define SMEM_TOTAL (4 * STAGE_BYTES)            // 196608

__device__ __forceinline__ void load_tile(uint32_t sbase, int i, int s,
                                          int m0, int n0, int tid)
{
    const int kt = i * 64;
    const uint32_t aoff = s * STAGE_BYTES;
    const uint32_t boff = aoff + STAGE_A;
#pragma unroll
    for (int r = 0; r < 4; r++) {
        const int idx = tid + r * 256;             // 0..1023
        const int row = idx >> 3, cc = idx & 7;
        const uint64_t src = __cvta_generic_to_global(g_A16 + (size_t)(m0 + row) * DIN + kt + cc * 8);
        CP_ASYNC16(sbase + aoff + SW128(row * 128 + cc * 16), src);
    }
#pragma unroll
    for (int r = 0; r < 8; r++) {
        const int idx = tid + r * 256;             // 0..2047
        const int row = idx >> 3, cc = idx & 7;
        const uint64_t src = __cvta_generic_to_global(g_B16 + (size_t)(n0 + row) * DIN + kt + cc * 8);
        CP_ASYNC16(sbase + boff + SW128(row * 128 + cc * 16), src);
    }
    CP_COMMIT();
}

__global__ __launch_bounds__(256, 1) void gemm_mma_kernel(const float* __restrict__ q)
{
    extern __shared__ char smem[];
    const uint32_t sbase = smem_u32(smem);
    const int tid  = threadIdx.x;
    const int w    = tid >> 5;
    const int lane = tid & 31;
    const int ny = blockIdx.x;              // 0..7 (fast: A-tile reuse in L2)
    const int m0 = blockIdx.y * 128;
    const int n0 = ny * 256;
    const int wm = w >> 2;                  // 0..1
    const int wn = w & 3;                   // 0..3

    float acc[4][8][4];
#pragma unroll
    for (int mi = 0; mi < 4; mi++)
#pragma unroll
        for (int n8 = 0; n8 < 8; n8++)
#pragma unroll
            for (int c = 0; c < 4; c++) acc[mi][n8][c] = 0.f;

    // prologue: stages 0,1,2 in flight
    load_tile(sbase, 0, 0, m0, n0, tid);
    load_tile(sbase, 1, 1, m0, n0, tid);
    load_tile(sbase, 2, 2, m0, n0, tid);

    // precomputed ldmatrix lane-address components
    const int aT  = lane >> 3;                       // 0..3
    const int arow_l = ((aT & 1) << 3) + (lane & 7); // +8 rows for odd T
    const int akb_l  = (aT >> 1) << 4;               // +16B for T>=2
    const int brow_l = (((lane >> 4) & 1) << 3) + (lane & 7);
    const int bkb_l  = ((lane >> 3) & 1) << 4;

    uint32_t afr[2][4][4];
    uint32_t bfr[2][8][2];

    for (int i = 0; i < NT; i++) {
        const int rem = NT - 1 - i;
        if (rem >= 2)      CP_WAIT(2);
        else if (rem == 1) CP_WAIT(1);
        else               CP_WAIT(0);
        __syncthreads();
        // load(i+3) targets stage (i+3)&3 == (i-1)&3; its readers (tile i-1)
        // are fenced by the barrier above.
        if (i + 3 < NT) load_tile(sbase, i + 3, (i + 3) & 3, m0, n0, tid);

        const uint32_t sA = sbase + (i & 3) * STAGE_BYTES;
        const uint32_t sB = sA + STAGE_A;

        // prefetch kk=0 fragments
#pragma unroll
        for (int mi = 0; mi < 4; mi++) {
            const int row = wm * 64 + mi * 16 + arow_l;
            LDSM_X4(afr[0][mi][0], afr[0][mi][1], afr[0][mi][2], afr[0][mi][3],
                    sA + SW128(row * 128 + akb_l));
        }
#pragma unroll
        for (int np = 0; np < 4; np++) {
            const int nrow = wn * 64 + np * 16 + brow_l;
            LDSM_X4(bfr[0][np * 2][0], bfr[0][np * 2][1],
                    bfr[0][np * 2 + 1][0], bfr[0][np * 2 + 1][1],
                    sB + SW128(nrow * 128 + bkb_l));
        }

#pragma unroll
        for (int kk = 0; kk < 4; kk++) {
            const int cur = kk & 1;
            const int nxt = cur ^ 1;
            if (kk < 3) {
                const int kb = (kk + 1) * 32;
#pragma unroll
                for (int mi = 0; mi < 4; mi++) {
                    const int row = wm * 64 + mi * 16 + arow_l;
                    LDSM_X4(afr[nxt][mi][0], afr[nxt][mi][1],
                            afr[nxt][mi][2], afr[nxt][mi][3],
                            sA + SW128(row * 128 + kb + akb_l));
                }
#pragma unroll
                for (int np = 0; np < 4; np++) {
                    const int nrow = wn * 64 + np * 16 + brow_l;
                    LDSM_X4(bfr[nxt][np * 2][0], bfr[nxt][np * 2][1],
                            bfr[nxt][np * 2 + 1][0], bfr[nxt][np * 2 + 1][1],
                            sB + SW128(nrow * 128 + kb + bkb_l));
                }
            }
#pragma unroll
            for (int mi = 0; mi < 4; mi++)
#pragma unroll
                for (int n8 = 0; n8 < 8; n8++)
                    MMA_16816(acc[mi][n8], afr[cur][mi], bfr[cur][n8]);
        }
    }
    __syncthreads();   // stage smem is reused as st_buf below

    // -----------------------------------------------------------------------
    // Epilogue A: relu, write v, per-row st partials to smem.
    // Column pairing: c0/c2 = k, c1/c3 = v.  d = (wn&1)*32 + n8*4 + (lane&3).
    // Head h = ny*2 + (wn>>1).
    // -----------------------------------------------------------------------
    const int h     = ny * 2 + (wn >> 1);
    const int dbase = (wn & 1) * 32 + (lane & 3);
    float qreg[8];
#pragma unroll
    for (int n8 = 0; n8 < 8; n8++) qreg[n8] = q[h * D_ + dbase + n8 * 4];

    float* st_buf = (float*)smem;                 // [128][4] per head-pair warp slot
    float* st_tot = (float*)(smem + 2048);        // [2][128] final st per head

#pragma unroll
    for (int mi = 0; mi < 4; mi++) {
        const int rl0 = wm * 64 + mi * 16 + (lane >> 2);
        float st0 = 0.f, st1 = 0.f;
#pragma unroll
        for (int n8 = 0; n8 < 8; n8++) {
            const int d = dbase + n8 * 4;
            const float k0 = fmaxf(acc[mi][n8][0], 0.f);
            const float v0 = fmaxf(acc[mi][n8][1], 0.f);
            const float k1 = fmaxf(acc[mi][n8][2], 0.f);
            const float v1 = fmaxf(acc[mi][n8][3], 0.f);
            st0 += qreg[n8] * k0;
            st1 += qreg[n8] * k1;
            {
                const int m = m0 + rl0;
                const int b = m >> 12, t = m & 4095;
                g_v[((size_t)(b * H_ + h) * T_ + t) * D_ + d] = v0;
            }
            {
                const int m = m0 + rl0 + 8;
                const int b = m >> 12, t = m & 4095;
                g_v[((size_t)(b * H_ + h) * T_ + t) * D_ + d] = v1;
            }
        }
        st0 += __shfl_xor_sync(0xffffffffu, st0, 1);
        st0 += __shfl_xor_sync(0xffffffffu, st0, 2);
        st1 += __shfl_xor_sync(0xffffffffu, st1, 1);
        st1 += __shfl_xor_sync(0xffffffffu, st1, 2);
        if ((lane & 3) == 0) {
            st_buf[rl0 * 4 + wn]       = st0;
            st_buf[(rl0 + 8) * 4 + wn] = st1;
        }
    }
    __syncthreads();

    if (tid < 128) {
        const int m = m0 + tid;
        const int b = m >> 12, t = m & 4095;
        const float s0 = st_buf[tid * 4 + 0] + st_buf[tid * 4 + 1];
        const float s1 = st_buf[tid * 4 + 2] + st_buf[tid * 4 + 3];
        g_st[(size_t)(b * H_ + ny * 2) * T_ + t]     = s0;
        g_st[(size_t)(b * H_ + ny * 2 + 1) * T_ + t] = s1;
        st_tot[tid]       = s0;
        st_tot[128 + tid] = s1;
    }
    __syncthreads();

    // -----------------------------------------------------------------------
    // Epilogue B (fused scan phase 1): commutative combine -> order-free
    // chunk-carry reduction. Warp (wm,wn): chunk wm, head h, d-range dbase.
    // -----------------------------------------------------------------------
    {
        const int hh = wn >> 1;
        const int r  = lane >> 2;
        float mloc = -FLT_MAX;
#pragma unroll
        for (int mi = 0; mi < 4; mi++) {
            mloc = fmaxf(mloc, st_tot[hh * 128 + wm * 64 + mi * 16 + r]);
            mloc = fmaxf(mloc, st_tot[hh * 128 + wm * 64 + mi * 16 + 8 + r]);
        }
        float uloc = 0.f, wloc[8];
#pragma unroll
        for (int n8 = 0; n8 < 8; n8++) wloc[n8] = 0.f;
#pragma unroll
        for (int mi = 0; mi < 4; mi++) {
            const float s0 = st_tot[hh * 128 + wm * 64 + mi * 16 + r];
            const float s1 = st_tot[hh * 128 + wm * 64 + mi * 16 + 8 + r];
            const float e0 = __expf(s0 - mloc);
            const float e1 = __expf(s1 - mloc);
            uloc += e0 + e1;
#pragma unroll
            for (int n8 = 0; n8 < 8; n8++) {
                wloc[n8] += e0 * fmaxf(acc[mi][n8][1], 0.f)
                          + e1 * fmaxf(acc[mi][n8][3], 0.f);
            }
        }
#pragma unroll
        for (int off = 4; off <= 16; off <<= 1) {
            const float m2 = __shfl_xor_sync(0xffffffffu, mloc, off);
            const float u2 = __shfl_xor_sync(0xffffffffu, uloc, off);
            const float mn = fmaxf(mloc, m2);
            const float ea = __expf(mloc - mn);
            const float eb = __expf(m2 - mn);
            uloc = uloc * ea + u2 * eb;
#pragma unroll
            for (int n8 = 0; n8 < 8; n8++) {
                const float w2 = __shfl_xor_sync(0xffffffffu, wloc[n8], off);
                wloc[n8] = wloc[n8] * ea + w2 * eb;
            }
            mloc = mn;
        }
        const int mrow0 = m0 + wm * 64;
        const int b = mrow0 >> 12;
        const int c = (mrow0 & 4095) >> 6;
        const size_t ci = (size_t)(b * H_ + h) * NC + c;
        if (r == 0) {
#pragma unroll
            for (int n8 = 0; n8 < 8; n8++)
                g_cw[ci * D_ + dbase + n8 * 4] = wloc[n8];
            if (lane == 0 && (wn & 1) == 0) { g_cm[ci] = mloc; g_cu[ci] = uloc; }
        }
    }
}

// ---------------------------------------------------------------------------
// Phase 2: per-(b,h) block, carries staged once through smem (verified win).
// ---------------------------------------------------------------------------
__global__ __launch_bounds__(64) void scan_phase2_kernel()
{
    __shared__ float sm_m[NC], sm_u[NC], sm_w[NC][D_];
    const int bh = blockIdx.x;
    const int d  = threadIdx.x;   // 0..63

    sm_m[d] = g_cm[(size_t)bh * NC + d];
    sm_u[d] = g_cu[(size_t)bh * NC + d];
    for (int c = 0; c < NC; c++)
        sm_w[c][d] = g_cw[((size_t)bh * NC + c) * D_ + d];
    __syncthreads();

    float m = -FLT_MAX, u = 0.f, w = 0.f;
    for (int c = 0; c < NC; c++) {
        const float cm = sm_m[c];
        const float cu = sm_u[c];
        const float cw = sm_w[c][d];
        g_cw[((size_t)bh * NC + c) * D_ + d] = w;
        if (d == 0) { g_cm[(size_t)bh * NC + c] = m; g_cu[(size_t)bh * NC + c] = u; }

        const float mn = fmaxf(m, cm);
        const float ea = __expf(m - mn);
        const float eb = __expf(cm - mn);
        u = u * ea + cu * eb;
        w = w * ea + cw * eb;
        m = mn;
    }
}

// ---------------------------------------------------------------------------
// Phase 3 (independent warps + REDG atomics — verified fastest variant):
// per-(b,h,chunk) warp re-scans its chunk from the chunk prefix,
// out[b,t,d] += w/u via atomicAdd.
// ---------------------------------------------------------------------------
__global__ __launch_bounds__(256) void scan_phase3_kernel(float* __restrict__ out)
{
    const int gw   = (blockIdx.x * blockDim.x + threadIdx.x) >> 5;
    const int lane = threadIdx.x & 31;
    const int c  = gw % NC;
    const int bh = gw / NC;
    const int b  = bh >> 4;

    const size_t ci = (size_t)bh * NC + c;
    float m  = g_cm[ci];
    float u  = g_cu[ci];
    float w0 = g_cw[ci * D_ + lane];
    float w1 = g_cw[ci * D_ + 32 + lane];

    const float* vp  = g_v  + ((size_t)bh * T_ + c * CH) * D_;
    const float* stp = g_st + (size_t)bh * T_ + c * CH;
    float* op = out + ((size_t)b * T_ + c * CH) * D_;

    for (int i = 0; i < CH; i++) {
        const float st = stp[i];
        const float v0 = vp[i * D_ + lane];
        const float v1 = vp[i * D_ + 32 + lane];
        const float mn = fmaxf(m, st);
        const float ea = __expf(m - mn);
        const float eb = __expf(st - mn);
        u  = u  * ea + eb;
        w0 = w0 * ea + v0 * eb;
        w1 = w1 * ea + v1 * eb;
        m = mn;
        const float inv = __fdividef(1.f, u);
        atomicAdd(&op[i * D_ + lane],      w0 * inv);
        atomicAdd(&op[i * D_ + 32 + lane], w1 * inv);
    }
}

// ---------------------------------------------------------------------------
extern "C" void kernel_launch(void* const* d_in, const int* in_sizes, int n_in,
                              void* d_out, int out_size)
{
    const float* inp = nullptr;
    const float* kvk = nullptr;
    const float* qk  = nullptr;
    for (int i = 0; i < n_in; i++) {
        if (in_sizes[i] == B_ * T_ * DIN)          inp = (const float*)d_in[i];
        else if (in_sizes[i] == DIN * H_ * D_ * 2) kvk = (const float*)d_in[i];
        else if (in_sizes[i] == H_ * D_)           qk  = (const float*)d_in[i];
    }
    float* out = (float*)d_out;

    cudaFuncSetAttribute(gemm_mma_kernel,
                         cudaFuncAttributeMaxDynamicSharedMemorySize, SMEM_TOTAL);

    cudaMemsetAsync(out, 0, (size_t)out_size * sizeof(float));

    convA_kernel<<<(M_ * DIN / 4) / 256, 256>>>(inp);
    convB_kernel<<<dim3(N_ / 32, DIN / 32), dim3(32, 8)>>>(kvk);

    dim3 ggrid(8, M_ / 128);
    gemm_mma_kernel<<<ggrid, 256, SMEM_TOTAL>>>(qk);

    scan_phase2_kernel<<<B_ * H_, 64>>>();
    scan_phase3_kernel<<<(B_ * H_ * NC) / 8, 256>>>(out);
}